// round 1
// baseline (speedup 1.0000x reference)
#include <cuda_runtime.h>
#include <math.h>

#define CH 128
#define N_NODES_MAX 10000
#define NODES_PER_BLK 16

// -------- scratch (no allocations allowed) --------
__device__ float g_agg[N_NODES_MAX * CH];   // scatter-add target, 5.12 MB
__device__ float g_deg[N_NODES_MAX];
__device__ int   g_hmax[CH];                // max over nodes of relu(h), as ordered ints (values >= 0)
__device__ int   g_is64;                    // 1 if edge_index is int64, 0 if int32

// -------- dtype sniffer: int64 node ids < 2^31 have zero high words --------
__global__ void sniff_kernel(const int* __restrict__ ei32) {
    int v = ei32[2 * threadIdx.x + 1];      // odd 32-bit words
    unsigned b = __ballot_sync(0xffffffffu, v != 0);
    if (threadIdx.x == 0) g_is64 = (b == 0) ? 1 : 0;
}

// -------- zero scratch --------
__global__ void zero_kernel(int n_nodes) {
    int i = blockIdx.x * blockDim.x + threadIdx.x;
    int nAgg4 = n_nodes * CH / 4;
    if (i < nAgg4) ((float4*)g_agg)[i] = make_float4(0.f, 0.f, 0.f, 0.f);
    if (i < n_nodes) g_deg[i] = 0.0f;
    if (i < CH) g_hmax[i] = 0;
}

// -------- edge kernel: one warp per edge; gather x[src] float4/lane, RED.128 scatter --------
__global__ void __launch_bounds__(256) edge_kernel(const float* __restrict__ x,
                                                   const void* __restrict__ ei, int E) {
    int warp = (blockIdx.x * blockDim.x + threadIdx.x) >> 5;
    if (warp >= E) return;
    int lane = threadIdx.x & 31;

    long long s, d;
    if (g_is64) {
        const long long* e64 = (const long long*)ei;
        s = __ldg(&e64[warp]);
        d = __ldg(&e64[E + warp]);
    } else {
        const int* e32 = (const int*)ei;
        s = (long long)__ldg(&e32[warp]);
        d = (long long)__ldg(&e32[E + warp]);
    }

    float4 v = __ldg((const float4*)(x + s * CH) + lane);
    float* dp = g_agg + d * CH + lane * 4;
    asm volatile("red.global.add.v4.f32 [%0], {%1, %2, %3, %4};"
                 :: "l"(dp), "f"(v.x), "f"(v.y), "f"(v.z), "f"(v.w) : "memory");
    if (lane == 0) atomicAdd(&g_deg[d], 1.0f);
}

// -------- node kernel: h = (agg/deg)@Wl + x@Wr + bl, relu, column-wise global max --------
__global__ void __launch_bounds__(128) node_kernel(const float* __restrict__ x,
                                                   const float* __restrict__ Wl,
                                                   const float* __restrict__ bl,
                                                   const float* __restrict__ Wr) {
    __shared__ float xs[NODES_PER_BLK * CH];
    __shared__ float ags[NODES_PER_BLK * CH];
    __shared__ float dinv[NODES_PER_BLK];

    int j = threadIdx.x;                    // output column 0..127
    int base = blockIdx.x * NODES_PER_BLK;  // first node of this tile

    if (j < NODES_PER_BLK)
        dinv[j] = 1.0f / fmaxf(g_deg[base + j], 1.0f);
    __syncthreads();

    const float4* x4 = (const float4*)(x + (size_t)base * CH);
    const float4* a4 = (const float4*)(g_agg + (size_t)base * CH);
#pragma unroll
    for (int t = 0; t < NODES_PER_BLK * CH / 4 / 128; t++) {
        int idx = j + t * 128;              // float4 index; 32 float4 per node row
        float4 xv = __ldg(&x4[idx]);
        float4 av = a4[idx];
        float sc = dinv[idx >> 5];
        av.x *= sc; av.y *= sc; av.z *= sc; av.w *= sc;
        ((float4*)xs)[idx] = xv;
        ((float4*)ags)[idx] = av;
    }
    __syncthreads();

    float acc[NODES_PER_BLK];
    float blj = __ldg(&bl[j]);
#pragma unroll
    for (int n = 0; n < NODES_PER_BLK; n++) acc[n] = blj;

#pragma unroll 4
    for (int k4 = 0; k4 < CH; k4 += 4) {
        float wl0 = __ldg(&Wl[(k4 + 0) * CH + j]);
        float wl1 = __ldg(&Wl[(k4 + 1) * CH + j]);
        float wl2 = __ldg(&Wl[(k4 + 2) * CH + j]);
        float wl3 = __ldg(&Wl[(k4 + 3) * CH + j]);
        float wr0 = __ldg(&Wr[(k4 + 0) * CH + j]);
        float wr1 = __ldg(&Wr[(k4 + 1) * CH + j]);
        float wr2 = __ldg(&Wr[(k4 + 2) * CH + j]);
        float wr3 = __ldg(&Wr[(k4 + 3) * CH + j]);
#pragma unroll
        for (int n = 0; n < NODES_PER_BLK; n++) {
            float4 a  = *(const float4*)&ags[n * CH + k4];
            float4 xv = *(const float4*)&xs[n * CH + k4];
            acc[n] += a.x * wl0 + a.y * wl1 + a.z * wl2 + a.w * wl3
                    + xv.x * wr0 + xv.y * wr1 + xv.z * wr2 + xv.w * wr3;
        }
    }

    float m = 0.0f;                          // relu folded: start at 0
#pragma unroll
    for (int n = 0; n < NODES_PER_BLK; n++) m = fmaxf(m, acc[n]);
    atomicMax(&g_hmax[j], __float_as_int(m));  // m >= 0 -> int order == float order
}

// -------- final head: news = relu(x0@W0+b0); z = relu(cat@W1+b1); out = z@W2+b2 --------
__global__ void __launch_bounds__(128) final_kernel(const float* __restrict__ x,
                                                    const float* __restrict__ W0,
                                                    const float* __restrict__ b0,
                                                    const float* __restrict__ W1,
                                                    const float* __restrict__ b1,
                                                    const float* __restrict__ W2,
                                                    const float* __restrict__ b2,
                                                    float* __restrict__ out) {
    __shared__ float x0s[CH];
    __shared__ float cat[2 * CH];
    __shared__ float p0[CH], p1[CH];

    int j = threadIdx.x;
    x0s[j] = x[j];                           // x row 0
    __syncthreads();

    float a = b0[j];
#pragma unroll 8
    for (int k = 0; k < CH; k++) a += x0s[k] * W0[k * CH + j];
    cat[j] = fmaxf(a, 0.0f);
    cat[CH + j] = __int_as_float(g_hmax[j]);
    __syncthreads();

    float z = b1[j];
#pragma unroll 8
    for (int k = 0; k < 2 * CH; k++) z += cat[k] * W1[k * CH + j];
    z = fmaxf(z, 0.0f);

    p0[j] = z * W2[j * 2 + 0];
    p1[j] = z * W2[j * 2 + 1];
    __syncthreads();
#pragma unroll
    for (int s = 64; s > 0; s >>= 1) {
        if (j < s) { p0[j] += p0[j + s]; p1[j] += p1[j + s]; }
        __syncthreads();
    }
    if (j == 0) { out[0] = p0[0] + b2[0]; out[1] = p1[0] + b2[1]; }
}

extern "C" void kernel_launch(void* const* d_in, const int* in_sizes, int n_in,
                              void* d_out, int out_size) {
    const float* x  = (const float*)d_in[0];
    const void*  ei = d_in[1];
    const float* Wl = (const float*)d_in[2];
    const float* bl = (const float*)d_in[3];
    const float* Wr = (const float*)d_in[4];
    const float* W0 = (const float*)d_in[5];
    const float* b0 = (const float*)d_in[6];
    const float* W1 = (const float*)d_in[7];
    const float* b1 = (const float*)d_in[8];
    const float* W2 = (const float*)d_in[9];
    const float* b2 = (const float*)d_in[10];
    float* out = (float*)d_out;

    int N = in_sizes[0] / CH;       // 10000
    int E = in_sizes[1] / 2;        // 640000

    sniff_kernel<<<1, 32>>>((const int*)ei);

    int zWork = N * CH / 4;         // 320000 threads also cover deg (N) and hmax (CH)
    zero_kernel<<<(zWork + 255) / 256, 256>>>(N);

    long long eThreads = (long long)E * 32;
    edge_kernel<<<(unsigned)((eThreads + 255) / 256), 256>>>(x, ei, E);

    node_kernel<<<N / NODES_PER_BLK, 128>>>(x, Wl, bl, Wr);

    final_kernel<<<1, 128>>>(x, W0, b0, W1, b1, W2, b2, out);
}

// round 2
// speedup vs baseline: 1.0418x; 1.0418x over previous
#include <cuda_runtime.h>
#include <math.h>

#define CH 128
#define N_NODES_MAX 10000
#define E_MAX 640000
#define NODES_PER_BLK 16

// -------- scratch (no allocations allowed) --------
__device__ float  g_agg[N_NODES_MAX * CH];     // normalized aggregate (mean)
__device__ int    g_cnt[N_NODES_MAX];          // per-dst degree
__device__ int    g_off[N_NODES_MAX + 1];      // CSR offsets
__device__ int    g_cur[N_NODES_MAX];          // scatter cursors
__device__ int    g_csr[E_MAX];                // CSR src ids
__device__ int    g_hmax[CH];                  // column-wise max of relu(h), ordered-int trick
__device__ int    g_is64;
__device__ float2 g_Wlp[(CH / 2) * CH];        // packed (Wl[k][j], Wl[k+1][j])
__device__ float2 g_Wrp[(CH / 2) * CH];

// -------- dtype sniffer: int64 node ids < 2^31 have zero high words --------
__global__ void sniff_kernel(const int* __restrict__ ei32) {
    int v = ei32[2 * threadIdx.x + 1];
    unsigned b = __ballot_sync(0xffffffffu, v != 0);
    if (threadIdx.x == 0) g_is64 = (b == 0) ? 1 : 0;
}

// -------- zero counters --------
__global__ void zero_kernel(int n_nodes) {
    int i = blockIdx.x * blockDim.x + threadIdx.x;
    if (i < n_nodes) g_cnt[i] = 0;
    if (i < CH) g_hmax[i] = 0;
}

// -------- pre-pack weights into (k, k+1) pairs per column --------
__global__ void prepack_kernel(const float* __restrict__ Wl, const float* __restrict__ Wr) {
    int i = blockIdx.x * blockDim.x + threadIdx.x;   // i in [0, 64*128)
    if (i >= (CH / 2) * CH) return;
    int k2 = i / CH, j = i % CH;
    g_Wlp[i] = make_float2(Wl[(2 * k2) * CH + j], Wl[(2 * k2 + 1) * CH + j]);
    g_Wrp[i] = make_float2(Wr[(2 * k2) * CH + j], Wr[(2 * k2 + 1) * CH + j]);
}

__device__ __forceinline__ void load_edge_dst(const void* ei, int E, int e, int& d) {
    if (g_is64) d = (int)__ldg(&((const long long*)ei)[E + e]);
    else        d = __ldg(&((const int*)ei)[E + e]);
}
__device__ __forceinline__ void load_edge(const void* ei, int E, int e, int& s, int& d) {
    if (g_is64) {
        s = (int)__ldg(&((const long long*)ei)[e]);
        d = (int)__ldg(&((const long long*)ei)[E + e]);
    } else {
        s = __ldg(&((const int*)ei)[e]);
        d = __ldg(&((const int*)ei)[E + e]);
    }
}

// -------- histogram of dst --------
__global__ void hist_kernel(const void* __restrict__ ei, int E) {
    int e = blockIdx.x * blockDim.x + threadIdx.x;
    if (e >= E) return;
    int d; load_edge_dst(ei, E, e, d);
    atomicAdd(&g_cnt[d], 1);
}

// -------- exclusive scan over counts (single 1024-thread block) --------
__global__ void __launch_bounds__(1024) scan_kernel(int N, int E) {
    __shared__ int s[1024];
    int tid = threadIdx.x;
    int chunk = (N + 1023) / 1024;
    int base = tid * chunk;
    int sum = 0;
    for (int i = 0; i < chunk; i++) {
        int idx = base + i;
        if (idx < N) sum += g_cnt[idx];
    }
    s[tid] = sum;
    __syncthreads();
    for (int st = 1; st < 1024; st <<= 1) {
        int v = (tid >= st) ? s[tid - st] : 0;
        __syncthreads();
        s[tid] += v;
        __syncthreads();
    }
    int run = (tid > 0) ? s[tid - 1] : 0;
    for (int i = 0; i < chunk; i++) {
        int idx = base + i;
        if (idx < N) {
            g_off[idx] = run;
            g_cur[idx] = run;
            run += g_cnt[idx];
        }
    }
    if (tid == 0) g_off[N] = E;
}

// -------- scatter src ids into CSR --------
__global__ void scatter_kernel(const void* __restrict__ ei, int E) {
    int e = blockIdx.x * blockDim.x + threadIdx.x;
    if (e >= E) return;
    int s, d; load_edge(ei, E, e, s, d);
    int slot = atomicAdd(&g_cur[d], 1);
    g_csr[slot] = s;
}

// -------- aggregate: one warp per dst node, pure gather, no atomics --------
__global__ void __launch_bounds__(256) agg_kernel(const float* __restrict__ x, int N) {
    int node = blockIdx.x * 8 + (threadIdx.x >> 5);
    if (node >= N) return;
    int lane = threadIdx.x & 31;
    int beg = g_off[node], end = g_off[node + 1];

    float4 acc = make_float4(0.f, 0.f, 0.f, 0.f);
    int e = beg;
    for (; e + 4 <= end; e += 4) {
        int i0 = __ldg(&g_csr[e + 0]);
        int i1 = __ldg(&g_csr[e + 1]);
        int i2 = __ldg(&g_csr[e + 2]);
        int i3 = __ldg(&g_csr[e + 3]);
        float4 v0 = __ldg((const float4*)(x + (size_t)i0 * CH) + lane);
        float4 v1 = __ldg((const float4*)(x + (size_t)i1 * CH) + lane);
        float4 v2 = __ldg((const float4*)(x + (size_t)i2 * CH) + lane);
        float4 v3 = __ldg((const float4*)(x + (size_t)i3 * CH) + lane);
        acc.x += v0.x + v1.x + v2.x + v3.x;
        acc.y += v0.y + v1.y + v2.y + v3.y;
        acc.z += v0.z + v1.z + v2.z + v3.z;
        acc.w += v0.w + v1.w + v2.w + v3.w;
    }
    for (; e < end; e++) {
        int i0 = __ldg(&g_csr[e]);
        float4 v0 = __ldg((const float4*)(x + (size_t)i0 * CH) + lane);
        acc.x += v0.x; acc.y += v0.y; acc.z += v0.z; acc.w += v0.w;
    }
    float inv = 1.0f / (float)max(end - beg, 1);
    acc.x *= inv; acc.y *= inv; acc.z *= inv; acc.w *= inv;
    ((float4*)(g_agg + (size_t)node * CH))[lane] = acc;
}

#define FFMA2(acc, a, b) \
    asm("fma.rn.f32x2 %0, %1, %2, %0;" : "+l"(acc) : "l"(a), "l"(b))

// -------- node GEMM: h = agg@Wl + x@Wr + bl, relu, column-wise global max --------
__global__ void __launch_bounds__(128) node_kernel(const float* __restrict__ x,
                                                   const float* __restrict__ bl) {
    __shared__ float xs[NODES_PER_BLK * CH];
    __shared__ float ags[NODES_PER_BLK * CH];

    int j = threadIdx.x;
    int base = blockIdx.x * NODES_PER_BLK;

    const float4* x4 = (const float4*)(x + (size_t)base * CH);
    const float4* a4 = (const float4*)(g_agg + (size_t)base * CH);
#pragma unroll
    for (int t = 0; t < NODES_PER_BLK * CH / 4 / 128; t++) {
        int idx = j + t * 128;
        ((float4*)xs)[idx] = __ldg(&x4[idx]);
        ((float4*)ags)[idx] = a4[idx];
    }
    __syncthreads();

    // packed accumulators: .lo = even-k partial, .hi = odd-k partial
    unsigned long long acc[NODES_PER_BLK];
#pragma unroll
    for (int n = 0; n < NODES_PER_BLK; n++) acc[n] = 0ull;

    const unsigned long long* wlp = (const unsigned long long*)g_Wlp;
    const unsigned long long* wrp = (const unsigned long long*)g_Wrp;

#pragma unroll 4
    for (int k4 = 0; k4 < CH; k4 += 4) {
        int k2 = k4 >> 1;
        unsigned long long wl01 = __ldg(&wlp[(k2 + 0) * CH + j]);
        unsigned long long wl23 = __ldg(&wlp[(k2 + 1) * CH + j]);
        unsigned long long wr01 = __ldg(&wrp[(k2 + 0) * CH + j]);
        unsigned long long wr23 = __ldg(&wrp[(k2 + 1) * CH + j]);
#pragma unroll
        for (int n = 0; n < NODES_PER_BLK; n++) {
            ulonglong2 a  = *(const ulonglong2*)(ags + n * CH + k4);
            ulonglong2 xv = *(const ulonglong2*)(xs + n * CH + k4);
            FFMA2(acc[n], a.x, wl01);
            FFMA2(acc[n], a.y, wl23);
            FFMA2(acc[n], xv.x, wr01);
            FFMA2(acc[n], xv.y, wr23);
        }
    }

    float blj = __ldg(&bl[j]);
    float m = 0.0f;   // relu folded
#pragma unroll
    for (int n = 0; n < NODES_PER_BLK; n++) {
        float lo = __int_as_float((int)(acc[n] & 0xffffffffull));
        float hi = __int_as_float((int)(acc[n] >> 32));
        m = fmaxf(m, lo + hi + blj);
    }
    atomicMax(&g_hmax[j], __float_as_int(m));
}

// -------- final head --------
__global__ void __launch_bounds__(128) final_kernel(const float* __restrict__ x,
                                                    const float* __restrict__ W0,
                                                    const float* __restrict__ b0,
                                                    const float* __restrict__ W1,
                                                    const float* __restrict__ b1,
                                                    const float* __restrict__ W2,
                                                    const float* __restrict__ b2,
                                                    float* __restrict__ out) {
    __shared__ float x0s[CH];
    __shared__ float cat[2 * CH];
    __shared__ float p0[CH], p1[CH];

    int j = threadIdx.x;
    x0s[j] = x[j];
    __syncthreads();

    float a = b0[j];
#pragma unroll 8
    for (int k = 0; k < CH; k++) a += x0s[k] * W0[k * CH + j];
    cat[j] = fmaxf(a, 0.0f);
    cat[CH + j] = __int_as_float(g_hmax[j]);
    __syncthreads();

    float z = b1[j];
#pragma unroll 8
    for (int k = 0; k < 2 * CH; k++) z += cat[k] * W1[k * CH + j];
    z = fmaxf(z, 0.0f);

    p0[j] = z * W2[j * 2 + 0];
    p1[j] = z * W2[j * 2 + 1];
    __syncthreads();
#pragma unroll
    for (int s = 64; s > 0; s >>= 1) {
        if (j < s) { p0[j] += p0[j + s]; p1[j] += p1[j + s]; }
        __syncthreads();
    }
    if (j == 0) { out[0] = p0[0] + b2[0]; out[1] = p1[0] + b2[1]; }
}

extern "C" void kernel_launch(void* const* d_in, const int* in_sizes, int n_in,
                              void* d_out, int out_size) {
    const float* x  = (const float*)d_in[0];
    const void*  ei = d_in[1];
    const float* Wl = (const float*)d_in[2];
    const float* bl = (const float*)d_in[3];
    const float* Wr = (const float*)d_in[4];
    const float* W0 = (const float*)d_in[5];
    const float* b0 = (const float*)d_in[6];
    const float* W1 = (const float*)d_in[7];
    const float* b1 = (const float*)d_in[8];
    const float* W2 = (const float*)d_in[9];
    const float* b2 = (const float*)d_in[10];
    float* out = (float*)d_out;

    int N = in_sizes[0] / CH;       // 10000
    int E = in_sizes[1] / 2;        // 640000

    sniff_kernel<<<1, 32>>>((const int*)ei);
    zero_kernel<<<(N + 255) / 256, 256>>>(N);
    prepack_kernel<<<((CH / 2) * CH + 255) / 256, 256>>>(Wl, Wr);
    hist_kernel<<<(E + 255) / 256, 256>>>(ei, E);
    scan_kernel<<<1, 1024>>>(N, E);
    scatter_kernel<<<(E + 255) / 256, 256>>>(ei, E);
    agg_kernel<<<(N + 7) / 8, 256>>>(x, N);
    node_kernel<<<N / NODES_PER_BLK, 128>>>(x, bl);
    final_kernel<<<1, 128>>>(x, W0, b0, W1, b1, W2, b2, out);
}